// round 1
// baseline (speedup 1.0000x reference)
#include <cuda_runtime.h>
#include <cuda_bf16.h>
#include <cstdint>

// Problem constants (shapes fixed by the dataset)
#define BB   16      // batch
#define CC   32      // channels in added; original has CC+1
#define HH   256     // grid H = W
#define TT   20      // boxes per batch
#define CELLS (HH*HH)           // 65536
#define VOX  0.8f
#define INVVOX 1.25f

// Scratch (no cudaMalloc allowed): 1MB mask + per-batch counters
__device__ uint4        g_maskv[BB * CELLS / 16];   // 16*65536 bytes, 16B aligned
__device__ unsigned int g_inter[BB];
__device__ unsigned int g_union[BB];

// ---------------------------------------------------------------------------
// K1: zero mask + counters (runs every call — graph replays must be clean)
// ---------------------------------------------------------------------------
__global__ void k_clear() {
    int idx = blockIdx.x * blockDim.x + threadIdx.x;   // 256*256 = 65536 threads
    g_maskv[idx] = make_uint4(0u, 0u, 0u, 0u);
    if (idx < BB) { g_inter[idx] = 0u; g_union[idx] = 0u; }
}

// ---------------------------------------------------------------------------
// K2: rasterize boxes into the byte mask. One CTA per (b, t) box.
// Exact same point-in-box predicate as the reference; AABB only prunes.
// ---------------------------------------------------------------------------
__global__ void k_rasterize(const float* __restrict__ boxes) {
    const int bt = blockIdx.x;            // 0 .. B*T-1
    const int b  = bt / TT;
    const float* bx = boxes + (size_t)bt * 7;

    const float cx = bx[0], cy = bx[1], cz = bx[2];
    const float dx = bx[3], dy = bx[4], dz = bx[5], yaw = bx[6];

    // z test is constant per box: |0.8 - cz| <= dz/2
    if (fabsf(VOX - cz) > 0.5f * dz) return;

    const float c  = cosf(yaw), s = sinf(yaw);
    const float hx = 0.5f * dx, hy = 0.5f * dy;

    // rotated-box AABB half extents (meters), +1 cell safety margin
    const float ax = hx * fabsf(c) + hy * fabsf(s);
    const float ay = hx * fabsf(s) + hy * fabsf(c);
    const int i0 = max(0,      (int)floorf((cx - ax) * INVVOX) - 1);
    const int i1 = min(HH - 1, (int)ceilf ((cx + ax) * INVVOX) + 1);
    const int j0 = max(0,      (int)floorf((cy - ay) * INVVOX) - 1);
    const int j1 = min(HH - 1, (int)ceilf ((cy + ay) * INVVOX) + 1);
    const int ni = i1 - i0 + 1, nj = j1 - j0 + 1;
    const int n  = ni * nj;

    unsigned char* mask = (unsigned char*)g_maskv + (size_t)b * CELLS;

    for (int k = threadIdx.x; k < n; k += blockDim.x) {
        const int i = i0 + k / nj;
        const int j = j0 + k % nj;
        const float px = (float)i * VOX - cx;       // shift_x
        const float py = (float)j * VOX - cy;       // shift_y
        const float rx = fmaf(py, s,  px * c);      //  px*c + py*s
        const float ry = fmaf(py, c, -px * s);      // -px*s + py*c
        if (fabsf(rx) < hx && fabsf(ry) < hy)
            mask[i * HH + j] = 1;                    // idempotent; races benign
    }
}

// ---------------------------------------------------------------------------
// K3: fused masked channel-reduce + IoU accumulate.
// grid = (64, B), block = 256; each thread owns 4 consecutive cells.
// Cells outside all boxes (~95%) skip ALL channel loads.
// ---------------------------------------------------------------------------
__global__ void k_iou(const float* __restrict__ added,
                      const float* __restrict__ orig) {
    const int b    = blockIdx.y;
    const int tid4 = blockIdx.x * blockDim.x + threadIdx.x;   // 0..16383
    const int cell0 = tid4 * 4;

    const unsigned int mword =
        ((const unsigned int*)g_maskv)[b * (CELLS / 4) + tid4];

    unsigned int inter = 0u, uni = 0u;

    if (mword != 0u) {
        const float* ap = added + ((size_t)b * CC) * CELLS + cell0;
        const float* op = orig  + ((size_t)b * (CC + 1) + 1) * CELLS + cell0;
        float4 sp = make_float4(0.f, 0.f, 0.f, 0.f);
        float4 so = make_float4(0.f, 0.f, 0.f, 0.f);
        #pragma unroll 8
        for (int ch = 0; ch < CC; ch++) {
            const float4 va = *(const float4*)(ap + (size_t)ch * CELLS);
            const float4 vo = *(const float4*)(op + (size_t)ch * CELLS);
            sp.x += va.x; sp.y += va.y; sp.z += va.z; sp.w += va.w;
            so.x += vo.x; so.y += vo.y; so.z += vo.z; so.w += vo.w;
        }
        const float spv[4] = {sp.x, sp.y, sp.z, sp.w};
        const float sov[4] = {so.x, so.y, so.z, so.w};
        #pragma unroll
        for (int k = 0; k < 4; k++) {
            const bool m = ((mword >> (8 * k)) & 0xFFu) != 0u;
            const bool p = m && (spv[k] != 0.0f);
            const bool o = m && (sov[k] != 0.0f);
            inter += (unsigned)(p && o);
            uni   += (unsigned)(p || o);
        }
    }

    // warp reduce
    inter = __reduce_add_sync(0xFFFFFFFFu, inter);
    uni   = __reduce_add_sync(0xFFFFFFFFu, uni);

    __shared__ unsigned int s_i[8], s_u[8];
    const int lane = threadIdx.x & 31;
    const int wid  = threadIdx.x >> 5;
    if (lane == 0) { s_i[wid] = inter; s_u[wid] = uni; }
    __syncthreads();
    if (wid == 0) {
        unsigned int vi = (lane < 8) ? s_i[lane] : 0u;
        unsigned int vu = (lane < 8) ? s_u[lane] : 0u;
        vi = __reduce_add_sync(0xFFFFFFFFu, vi);
        vu = __reduce_add_sync(0xFFFFFFFFu, vu);
        if (lane == 0 && (vi | vu)) {
            atomicAdd(&g_inter[b], vi);
            atomicAdd(&g_union[b], vu);
        }
    }
}

// ---------------------------------------------------------------------------
// K4: finalize -> out[0] = T * sum_b(inter/max(union,1)) / B
// ---------------------------------------------------------------------------
__global__ void k_final(float* __restrict__ out) {
    const int t = threadIdx.x;   // 32 threads
    float iou = 0.0f;
    if (t < BB) {
        const float un = (float)g_union[t];
        iou = (float)g_inter[t] / fmaxf(un, 1.0f);
    }
    #pragma unroll
    for (int off = 16; off > 0; off >>= 1)
        iou += __shfl_xor_sync(0xFFFFFFFFu, iou, off);
    if (t == 0)
        out[0] = (float)TT * iou / (float)BB;
}

// ---------------------------------------------------------------------------
extern "C" void kernel_launch(void* const* d_in, const int* in_sizes, int n_in,
                              void* d_out, int out_size) {
    const float* added = (const float*)d_in[0];   // (16,32,256,256)
    const float* orig  = (const float*)d_in[1];   // (16,33,256,256)
    const float* boxes = (const float*)d_in[2];   // (16,20,7)
    (void)in_sizes; (void)n_in; (void)out_size;   // tf_ego (d_in[3]) unused

    k_clear<<<256, 256>>>();
    k_rasterize<<<BB * TT, 256>>>(boxes);
    k_iou<<<dim3(64, BB), 256>>>(added, orig);
    k_final<<<1, 32>>>((float*)d_out);
}